// round 14
// baseline (speedup 1.0000x reference)
#include <cuda_runtime.h>

#define BB 8
#define NN 4096
#define NPTS (BB*NN)
#define KK 20
#define EPS_BN 1e-5f
#define GSZF 1536

// ---- scratch (device globals; no allocation allowed) ----
__device__ float g_xx[NPTS];
__device__ int   g_idx[NPTS*KK];
__device__ float g_x1[NPTS*64];
__device__ float g_x2[NPTS*64];
__device__ float g_x3[NPTS*64];
__device__ float g_cat[(size_t)NPTS*192];
__device__ float g_h7[(size_t)NPTS*512];
__device__ float g_h8[(size_t)NPTS*256];
__device__ float g_gmean[BB*1024];
__device__ float g_part[256*1024];
__device__ float g_b7[BB*512];

// ---- tf32 helpers (verified in R5) ----
__device__ __forceinline__ unsigned tf32_of(float a) {
    unsigned r; asm("cvt.rna.tf32.f32 %0, %1;" : "=r"(r) : "f"(a)); return r;
}
__device__ __forceinline__ void mma_tf32(float* c, const unsigned* a, const unsigned* b) {
    asm("mma.sync.aligned.m16n8k8.row.col.f32.tf32.tf32.f32 "
        "{%0,%1,%2,%3}, {%4,%5,%6,%7}, {%8,%9}, {%0,%1,%2,%3};"
        : "+f"(c[0]), "+f"(c[1]), "+f"(c[2]), "+f"(c[3])
        : "r"(a[0]), "r"(a[1]), "r"(a[2]), "r"(a[3]), "r"(b[0]), "r"(b[1]));
}

// ---- kNN for C=3 with xx fused ----
__global__ __launch_bounds__(128) void knn3_kernel(const float* __restrict__ x,
                                                   int* __restrict__ idxout) {
    constexpr int TILE = 128;
    constexpr int C = 3;
    __shared__ float xs[TILE*C];
    __shared__ float xxs[TILE];
    int tid = threadIdx.x;
    int gpt = blockIdx.x*128 + tid;
    int b = gpt >> 12;
    const float* xb = x + (size_t)b*NN*C;

    float q[C];
    #pragma unroll
    for (int c = 0; c < C; ++c) q[c] = x[(size_t)gpt*C + c];
    float qq = fmaf(q[2], q[2], fmaf(q[1], q[1], fmaf(q[0], q[0], 0.f)));

    float tv[KK]; int ti[KK];
    #pragma unroll
    for (int s = 0; s < KK; ++s) { tv[s] = -3.4e38f; ti[s] = 0; }

    for (int m0 = 0; m0 < NN; m0 += TILE) {
        __syncthreads();
        for (int l = tid; l < TILE*C; l += 128) xs[l] = xb[(size_t)m0*C + l];
        __syncthreads();
        {
            float v0 = xs[tid*3], v1 = xs[tid*3+1], v2 = xs[tid*3+2];
            xxs[tid] = fmaf(v2, v2, fmaf(v1, v1, fmaf(v0, v0, 0.f)));
        }
        __syncthreads();
        #pragma unroll 2
        for (int mm = 0; mm < TILE; ++mm) {
            float dot = 0.f;
            #pragma unroll
            for (int c = 0; c < C; ++c) dot = fmaf(q[c], xs[mm*C + c], dot);
            float v = 2.0f*dot - qq - xxs[mm];
            if (v > tv[KK-1]) {
                float cv = v; int ci = m0 + mm;
                #pragma unroll
                for (int s = 0; s < KK; ++s) {
                    if (cv > tv[s]) {
                        float t1 = tv[s]; int t2 = ti[s];
                        tv[s] = cv; ti[s] = ci; cv = t1; ci = t2;
                    }
                }
            }
        }
    }
    #pragma unroll
    for (int s = 0; s < KK; ++s) idxout[(size_t)gpt*KK + s] = ti[s];
}

// ---- kNN C=64 via 3xTF32 tensor-core distance tiles ----
// block = 64 queries, 128 threads (4 warps; warp w owns query rows 16w..16w+15)
__global__ __launch_bounds__(128) void knn64t_kernel(const float* __restrict__ x,
                                                     const float* __restrict__ xx,
                                                     int* __restrict__ idxout) {
    extern __shared__ float sh[];
    float* Qsm = sh;                 // [64][67] fp32, k-major: Qsm[c*67+q]
    float* Bh  = Qsm + 64*67;        // [64][67] tf32-hi of candidates, k-major
    float* Bl  = Bh  + 64*67;        // [64][67] tf32-lo
    float* Dsm = Bl  + 64*67;        // [64][65] D[q][m]
    float* xxs = Dsm + 64*65;        // [64]

    int tid = threadIdx.x;
    int warp = tid >> 5, lane = tid & 31;
    int gid = lane >> 2, tig = lane & 3;
    int q0 = blockIdx.x*64;          // global query base
    int b = q0 >> 12;
    const float* xb  = x  + (size_t)b*NN*64;
    const float* xxb = xx + (size_t)b*NN;
    int qbase = warp*16;

    // stage Q transposed (one-time)
    for (int l = tid; l < 64*64; l += 128) {
        int qq_ = l >> 6, c = l & 63;
        Qsm[c*67 + qq_] = x[(size_t)(q0 + qq_)*64 + c];
    }
    __syncthreads();

    // build A fragments hi/lo in registers (R5-verified mapping)
    unsigned ah[8][4], al[8][4];
    #pragma unroll
    for (int ks = 0; ks < 8; ++ks) {
        #pragma unroll
        for (int r = 0; r < 4; ++r) {
            int k = ks*8 + tig + ((r & 2) ? 4 : 0);
            int row = qbase + gid + ((r & 1) ? 8 : 0);
            float v = Qsm[k*67 + row];
            float hi = __uint_as_float(tf32_of(v));
            ah[ks][r] = __float_as_uint(hi);
            al[ks][r] = tf32_of(v - hi);
        }
    }

    float tv[KK]; int ti[KK]; float qq = 0.f;
    #pragma unroll
    for (int s = 0; s < KK; ++s) { tv[s] = -3.4e38f; ti[s] = 0; }
    if (tid < 64) qq = xx[q0 + tid];

    for (int m0 = 0; m0 < NN; m0 += 64) {
        __syncthreads();   // prev-iter scan done before overwriting B/xxs
        for (int l = tid; l < 64*64; l += 128) {
            int m = l >> 6, c = l & 63;
            float v = xb[(size_t)(m0 + m)*64 + c];
            float hi = __uint_as_float(tf32_of(v));
            Bh[c*67 + m] = hi;
            Bl[c*67 + m] = __uint_as_float(tf32_of(v - hi));
        }
        if (tid < 64) xxs[tid] = xxb[m0 + tid];
        __syncthreads();

        #pragma unroll
        for (int nt = 0; nt < 8; ++nt) {
            float acc[4] = {0.f, 0.f, 0.f, 0.f};
            int n = nt*8 + gid;
            #pragma unroll
            for (int ks = 0; ks < 8; ++ks) {
                int k0_ = ks*8 + tig;
                unsigned bh[2], bl[2];
                bh[0] = __float_as_uint(Bh[k0_*67 + n]);
                bh[1] = __float_as_uint(Bh[(k0_+4)*67 + n]);
                bl[0] = __float_as_uint(Bl[k0_*67 + n]);
                bl[1] = __float_as_uint(Bl[(k0_+4)*67 + n]);
                mma_tf32(acc, ah[ks], bl);
                mma_tf32(acc, al[ks], bh);
                mma_tf32(acc, ah[ks], bh);
            }
            int row = qbase + gid;
            int col = nt*8 + 2*tig;
            Dsm[row*65 + col]       = acc[0];
            Dsm[row*65 + col + 1]   = acc[1];
            Dsm[(row+8)*65 + col]     = acc[2];
            Dsm[(row+8)*65 + col + 1] = acc[3];
        }
        __syncthreads();

        if (tid < 64) {
            const float* drow = Dsm + tid*65;
            #pragma unroll 4
            for (int j = 0; j < 64; ++j) {
                float v = 2.0f*drow[j] - qq - xxs[j];
                if (v > tv[KK-1]) {
                    float cv = v; int ci = m0 + j;
                    #pragma unroll
                    for (int s = 0; s < KK; ++s) {
                        if (cv > tv[s]) {
                            float t1 = tv[s]; int t2 = ti[s];
                            tv[s] = cv; ti[s] = ci; cv = t1; ci = t2;
                        }
                    }
                }
            }
        }
    }
    if (tid < 64) {
        #pragma unroll
        for (int s = 0; s < KK; ++s) idxout[(size_t)(q0 + tid)*KK + s] = ti[s];
    }
}

// ---- fused edge-conv, warp-per-point (R13 winner, unchanged) ----
template<int CIN, bool TWO>
__global__ __launch_bounds__(256) void edgeconv_kernel(
    const float* __restrict__ x, const int* __restrict__ nbr,
    const float* __restrict__ Wa, const float* __restrict__ bna,
    const float* __restrict__ Wb, const float* __restrict__ bnb,
    float* __restrict__ out, float* __restrict__ xxout)
{
    constexpr int C2 = 2*CIN;
    extern __shared__ float sm[];
    float* Wat2 = sm;
    float* Wbt2 = Wat2 + C2*64;
    float* bnAs = Wbt2 + (TWO ? 4096 : 0);
    float* bnBs = bnAs + 192;
    float* grp  = bnBs + (TWO ? 192 : 0);

    int tid = threadIdx.x;
    int warp = tid >> 5, o = tid & 31;

    for (int l = tid; l < C2*32; l += 256) {
        int c = l >> 5, o2 = l & 31;
        ((float2*)Wat2)[c*32 + o2] = make_float2(Wa[(size_t)o2*C2 + c], Wa[(size_t)(o2+32)*C2 + c]);
    }
    if (TWO)
        for (int l = tid; l < 64*32; l += 256) {
            int c = l >> 5, o2 = l & 31;
            ((float2*)Wbt2)[c*32 + o2] = make_float2(Wb[(size_t)o2*64 + c], Wb[(size_t)(o2+32)*64 + c]);
        }
    if (tid < 64) {
        float ga = bna[tid], bt = bna[64+tid], mu = bna[128+tid], va = bna[192+tid];
        bnAs[tid] = ga*rsqrtf(va + EPS_BN); bnAs[64+tid] = mu; bnAs[128+tid] = bt;
    } else if (TWO && tid < 128) {
        int t = tid - 64;
        float ga = bnb[t], bt = bnb[64+t], mu = bnb[128+t], va = bnb[192+t];
        bnBs[t] = ga*rsqrtf(va + EPS_BN); bnBs[64+t] = mu; bnBs[128+t] = bt;
    }
    __syncthreads();

    float* gbuf = grp + warp*GSZF;
    float* gcen = gbuf + 20*72;
    int*   gsnb = (int*)(gcen + 68);

    float sA0 = bnAs[o],    mA0 = bnAs[64+o],    bA0 = bnAs[128+o];
    float sA1 = bnAs[o+32], mA1 = bnAs[64+o+32], bA1 = bnAs[128+o+32];
    float sB0=0.f,mB0=0.f,bB0=0.f,sB1=0.f,mB1=0.f,bB1=0.f;
    if (TWO) {
        sB0 = bnBs[o];    mB0 = bnBs[64+o];    bB0 = bnBs[128+o];
        sB1 = bnBs[o+32]; mB1 = bnBs[64+o+32]; bB1 = bnBs[128+o+32];
    }

    int base = (blockIdx.x*8 + warp) * 4;
    for (int p = 0; p < 4; ++p) {
        int gpt = base + p;
        int brow = (gpt >> 12) << 12;
        if (CIN == 64) {
            gcen[o]      = x[(size_t)gpt*CIN + o];
            gcen[o + 32] = x[(size_t)gpt*CIN + o + 32];
        } else {
            if (o < CIN) gcen[o] = x[(size_t)gpt*CIN + o];
        }
        if (o < KK) gsnb[o] = nbr[(size_t)gpt*KK + o];
        __syncwarp();
        if (CIN == 64) {
            float ce0 = gcen[o], ce1 = gcen[o+32];
            #pragma unroll
            for (int j = 0; j < KK; ++j) {
                const float* xr = x + ((size_t)(brow + gsnb[j]))*CIN;
                gbuf[j*72 + o]      = xr[o]      - ce0;
                gbuf[j*72 + o + 32] = xr[o + 32] - ce1;
            }
        } else {
            for (int l = o; l < 3*KK; l += 32) {
                int j = l / 3, c = l - 3*j;
                gbuf[j*72 + c] = x[((size_t)(brow + gsnb[j]))*CIN + c] - gcen[c];
            }
        }
        __syncwarp();
        float cd0 = 0.f, cd1 = 0.f;
        if (CIN == 64) {
            #pragma unroll 4
            for (int c4 = 0; c4 < CIN/4; ++c4) {
                float4 ce = *(const float4*)(gcen + 4*c4);
                float2 w0 = ((const float2*)Wat2)[(CIN + 4*c4 + 0)*32 + o];
                float2 w1 = ((const float2*)Wat2)[(CIN + 4*c4 + 1)*32 + o];
                float2 w2 = ((const float2*)Wat2)[(CIN + 4*c4 + 2)*32 + o];
                float2 w3 = ((const float2*)Wat2)[(CIN + 4*c4 + 3)*32 + o];
                cd0 = fmaf(w0.x, ce.x, cd0); cd1 = fmaf(w0.y, ce.x, cd1);
                cd0 = fmaf(w1.x, ce.y, cd0); cd1 = fmaf(w1.y, ce.y, cd1);
                cd0 = fmaf(w2.x, ce.z, cd0); cd1 = fmaf(w2.y, ce.z, cd1);
                cd0 = fmaf(w3.x, ce.w, cd0); cd1 = fmaf(w3.y, ce.w, cd1);
            }
        } else {
            #pragma unroll
            for (int c = 0; c < CIN; ++c) {
                float2 w = ((const float2*)Wat2)[(CIN + c)*32 + o];
                float ce = gcen[c];
                cd0 = fmaf(w.x, ce, cd0); cd1 = fmaf(w.y, ce, cd1);
            }
        }
        float acc0[KK], acc1[KK];
        #pragma unroll
        for (int j = 0; j < KK; ++j) { acc0[j] = cd0; acc1[j] = cd1; }
        if (CIN == 64) {
            #pragma unroll 1
            for (int c4 = 0; c4 < CIN/4; ++c4) {
                float2 w0 = ((const float2*)Wat2)[(4*c4 + 0)*32 + o];
                float2 w1 = ((const float2*)Wat2)[(4*c4 + 1)*32 + o];
                float2 w2 = ((const float2*)Wat2)[(4*c4 + 2)*32 + o];
                float2 w3 = ((const float2*)Wat2)[(4*c4 + 3)*32 + o];
                #pragma unroll
                for (int j = 0; j < KK; ++j) {
                    float4 d = *(const float4*)(gbuf + j*72 + 4*c4);
                    float a0 = acc0[j], a1 = acc1[j];
                    a0 = fmaf(w0.x, d.x, a0); a1 = fmaf(w0.y, d.x, a1);
                    a0 = fmaf(w1.x, d.y, a0); a1 = fmaf(w1.y, d.y, a1);
                    a0 = fmaf(w2.x, d.z, a0); a1 = fmaf(w2.y, d.z, a1);
                    a0 = fmaf(w3.x, d.w, a0); a1 = fmaf(w3.y, d.w, a1);
                    acc0[j] = a0; acc1[j] = a1;
                }
            }
        } else {
            #pragma unroll
            for (int c = 0; c < CIN; ++c) {
                float2 w = ((const float2*)Wat2)[c*32 + o];
                #pragma unroll
                for (int j = 0; j < KK; ++j) {
                    float d = gbuf[j*72 + c];
                    acc0[j] = fmaf(w.x, d, acc0[j]);
                    acc1[j] = fmaf(w.y, d, acc1[j]);
                }
            }
        }
        float vm0 = -3.4e38f, vm1 = -3.4e38f;
        if (TWO) {
            __syncwarp();
            #pragma unroll
            for (int j = 0; j < KK; ++j) {
                float y0 = (acc0[j] - mA0)*sA0 + bA0; y0 = (y0 >= 0.f) ? y0 : 0.2f*y0;
                float y1 = (acc1[j] - mA1)*sA1 + bA1; y1 = (y1 >= 0.f) ? y1 : 0.2f*y1;
                gbuf[j*72 + o]      = y0;
                gbuf[j*72 + o + 32] = y1;
            }
            __syncwarp();
            float a20[KK], a21[KK];
            #pragma unroll
            for (int j = 0; j < KK; ++j) { a20[j] = 0.f; a21[j] = 0.f; }
            #pragma unroll 1
            for (int c4 = 0; c4 < 16; ++c4) {
                float2 w0 = ((const float2*)Wbt2)[(4*c4 + 0)*32 + o];
                float2 w1 = ((const float2*)Wbt2)[(4*c4 + 1)*32 + o];
                float2 w2 = ((const float2*)Wbt2)[(4*c4 + 2)*32 + o];
                float2 w3 = ((const float2*)Wbt2)[(4*c4 + 3)*32 + o];
                #pragma unroll
                for (int j = 0; j < KK; ++j) {
                    float4 d = *(const float4*)(gbuf + j*72 + 4*c4);
                    float a0 = a20[j], a1 = a21[j];
                    a0 = fmaf(w0.x, d.x, a0); a1 = fmaf(w0.y, d.x, a1);
                    a0 = fmaf(w1.x, d.y, a0); a1 = fmaf(w1.y, d.y, a1);
                    a0 = fmaf(w2.x, d.z, a0); a1 = fmaf(w2.y, d.z, a1);
                    a0 = fmaf(w3.x, d.w, a0); a1 = fmaf(w3.y, d.w, a1);
                    a20[j] = a0; a21[j] = a1;
                }
            }
            #pragma unroll
            for (int j = 0; j < KK; ++j) {
                float y0 = (a20[j] - mB0)*sB0 + bB0; y0 = (y0 >= 0.f) ? y0 : 0.2f*y0;
                float y1 = (a21[j] - mB1)*sB1 + bB1; y1 = (y1 >= 0.f) ? y1 : 0.2f*y1;
                vm0 = fmaxf(vm0, y0); vm1 = fmaxf(vm1, y1);
            }
        } else {
            #pragma unroll
            for (int j = 0; j < KK; ++j) {
                float y0 = (acc0[j] - mA0)*sA0 + bA0; y0 = (y0 >= 0.f) ? y0 : 0.2f*y0;
                float y1 = (acc1[j] - mA1)*sA1 + bA1; y1 = (y1 >= 0.f) ? y1 : 0.2f*y1;
                vm0 = fmaxf(vm0, y0); vm1 = fmaxf(vm1, y1);
            }
        }
        out[(size_t)gpt*64 + o]      = vm0;
        out[(size_t)gpt*64 + o + 32] = vm1;
        if (xxout) {
            float sq = fmaf(vm1, vm1, vm0*vm0);
            #pragma unroll
            for (int off = 16; off; off >>= 1)
                sq += __shfl_down_sync(0xffffffffu, sq, off);
            if (o == 0) xxout[gpt] = sq;
        }
        __syncwarp();
    }
}

// ---- dense GEMM (R12/R13 version with colsum fusion) ----
__global__ __launch_bounds__(256) void gemm_kernel(
    const float* __restrict__ A, int lda,
    const float* __restrict__ W, int ldw,
    const float* __restrict__ bn, const float* __restrict__ bias,
    float* __restrict__ out, int Ncols, int Kd, int act,
    float* __restrict__ colsum)
{
    __shared__ float As[8][128];
    __shared__ float Ws[8][128];
    __shared__ float red[16][128];
    int tid = threadIdx.x;
    int bm  = blockIdx.y*128, bn0 = blockIdx.x*128;
    int lr = tid >> 1;
    int lk = (tid & 1)*4;
    int ty = tid >> 4, tx = tid & 15;

    float acc[8][8];
    #pragma unroll
    for (int i = 0; i < 8; ++i)
        #pragma unroll
        for (int j = 0; j < 8; ++j) acc[i][j] = 0.f;

    const float* Ap = A + (size_t)(bm + lr)*lda + lk;
    const float* Wp = W + (size_t)(bn0 + lr)*ldw + lk;

    for (int k0 = 0; k0 < Kd; k0 += 8) {
        float4 av = *(const float4*)(Ap + k0);
        float4 wv = *(const float4*)(Wp + k0);
        __syncthreads();
        As[lk+0][lr] = av.x; As[lk+1][lr] = av.y; As[lk+2][lr] = av.z; As[lk+3][lr] = av.w;
        Ws[lk+0][lr] = wv.x; Ws[lk+1][lr] = wv.y; Ws[lk+2][lr] = wv.z; Ws[lk+3][lr] = wv.w;
        __syncthreads();
        #pragma unroll
        for (int k = 0; k < 8; ++k) {
            float a[8], bb[8];
            *(float4*)(a)    = *(const float4*)&As[k][ty*8];
            *(float4*)(a+4)  = *(const float4*)&As[k][ty*8+4];
            *(float4*)(bb)   = *(const float4*)&Ws[k][tx*8];
            *(float4*)(bb+4) = *(const float4*)&Ws[k][tx*8+4];
            #pragma unroll
            for (int i = 0; i < 8; ++i)
                #pragma unroll
                for (int j = 0; j < 8; ++j) acc[i][j] = fmaf(a[i], bb[j], acc[i][j]);
        }
    }

    float sc[8], mu[8], be[8], bv[8];
    #pragma unroll
    for (int j = 0; j < 8; ++j) {
        int col = bn0 + tx*8 + j;
        if (act) {
            float ga = bn[col], bt = bn[Ncols+col], m = bn[2*Ncols+col], va = bn[3*Ncols+col];
            sc[j] = ga*rsqrtf(va + EPS_BN); mu[j] = m; be[j] = bt;
        }
        bv[j] = bias ? bias[(bm >> 12)*Ncols + col] : 0.f;
    }
    if (colsum) {
        float ps[8];
        #pragma unroll
        for (int j = 0; j < 8; ++j) ps[j] = 0.f;
        #pragma unroll
        for (int i = 0; i < 8; ++i)
            #pragma unroll
            for (int j = 0; j < 8; ++j) {
                float y = acc[i][j] + bv[j];
                if (act) { y = (y - mu[j])*sc[j] + be[j]; y = (y >= 0.f) ? y : 0.2f*y; }
                ps[j] += y;
            }
        #pragma unroll
        for (int j = 0; j < 8; ++j) red[ty][tx*8 + j] = ps[j];
        __syncthreads();
        if (tid < 128) {
            float s = 0.f;
            #pragma unroll
            for (int t = 0; t < 16; ++t) s += red[t][tid];
            colsum[(size_t)blockIdx.y*Ncols + bn0 + tid] = s;
        }
    } else {
        #pragma unroll
        for (int i = 0; i < 8; ++i) {
            int row = bm + ty*8 + i;
            float* orow = out + (size_t)row*Ncols + bn0 + tx*8;
            #pragma unroll
            for (int j = 0; j < 8; ++j) {
                float y = acc[i][j] + bv[j];
                if (act) { y = (y - mu[j])*sc[j] + be[j]; y = (y >= 0.f) ? y : 0.2f*y; }
                orow[j] = y;
            }
        }
    }
}

// ---- concat [x1|x2|x3] -> 192 ----
__global__ __launch_bounds__(256) void concat192_kernel(
    const float* __restrict__ x1, const float* __restrict__ x2,
    const float* __restrict__ x3, float* __restrict__ cat)
{
    int i = blockIdx.x*256 + threadIdx.x;
    int pt = i / 192, c = i - pt*192;
    float v;
    if (c < 64)       v = x1[(size_t)pt*64 + c];
    else if (c < 128) v = x2[(size_t)pt*64 + c - 64];
    else              v = x3[(size_t)pt*64 + c - 128];
    cat[i] = v;
}

// ---- mean from per-block column sums ----
__global__ __launch_bounds__(256) void mean2_kernel(const float* __restrict__ part,
                                                    float* __restrict__ gmean,
                                                    float* __restrict__ outg) {
    int i = blockIdx.x*256 + threadIdx.x;
    int b = i >> 10, c = i & 1023;
    float s = 0.f;
    #pragma unroll
    for (int t = 0; t < 32; ++t) s += part[((size_t)(b*32 + t) << 10) + c];
    s *= (1.0f/NN);
    gmean[i] = s;
    outg[i] = s;
}

// ---- b7[b,o] = sum_{c<1024} W7[o,c] * g[b,c] ----
__global__ __launch_bounds__(256) void bias7_kernel(const float* __restrict__ gm,
                                                    const float* __restrict__ W7,
                                                    float* __restrict__ b7) {
    int w = (blockIdx.x*256 + threadIdx.x) >> 5;
    int lane = threadIdx.x & 31;
    int b = w >> 9, o = w & 511;
    const float* gr = gm + (b << 10);
    const float* wr = W7 + (size_t)o*1216;
    float s = 0.f;
    #pragma unroll 4
    for (int c = lane; c < 1024; c += 32) s = fmaf(wr[c], gr[c], s);
    #pragma unroll
    for (int off = 16; off; off >>= 1) s += __shfl_down_sync(0xffffffffu, s, off);
    if (lane == 0) b7[(b << 9) + o] = s;
}

// ---- final 256 -> 3 projection ----
__global__ __launch_bounds__(256) void final_kernel(const float* __restrict__ h,
                                                    const float* __restrict__ W9,
                                                    float* __restrict__ out) {
    int warp = (blockIdx.x*256 + threadIdx.x) >> 5;
    int lane = threadIdx.x & 31;
    const float* hr = h + (size_t)warp*256;
    float p0 = 0.f, p1 = 0.f, p2 = 0.f;
    #pragma unroll
    for (int c0 = 0; c0 < 256; c0 += 32) {
        int c = c0 + lane;
        float hv = hr[c];
        p0 = fmaf(hv, W9[c],       p0);
        p1 = fmaf(hv, W9[256 + c], p1);
        p2 = fmaf(hv, W9[512 + c], p2);
    }
    #pragma unroll
    for (int off = 16; off; off >>= 1) {
        p0 += __shfl_down_sync(0xffffffffu, p0, off);
        p1 += __shfl_down_sync(0xffffffffu, p1, off);
        p2 += __shfl_down_sync(0xffffffffu, p2, off);
    }
    if (lane == 0) {
        out[(size_t)warp*3 + 0] = p0;
        out[(size_t)warp*3 + 1] = p1;
        out[(size_t)warp*3 + 2] = p2;
    }
}

static int ec_smem(int cin, bool two) {
    int c2 = 2*cin;
    return (c2*64 + (two ? 4096 : 0) + 192 + (two ? 192 : 0) + 8*GSZF) * 4;
}

extern "C" void kernel_launch(void* const* d_in, const int* in_sizes, int n_in,
                              void* d_out, int out_size) {
    (void)in_sizes; (void)n_in; (void)out_size;
    const float* x  = (const float*)d_in[0];
    const float* W1 = (const float*)d_in[1];
    const float* W2 = (const float*)d_in[2];
    const float* W3 = (const float*)d_in[3];
    const float* W4 = (const float*)d_in[4];
    const float* W5 = (const float*)d_in[5];
    const float* W6 = (const float*)d_in[6];
    const float* W7 = (const float*)d_in[7];
    const float* W8 = (const float*)d_in[8];
    const float* W9 = (const float*)d_in[9];
    const float* bn1 = (const float*)d_in[10];
    const float* bn2 = (const float*)d_in[11];
    const float* bn3 = (const float*)d_in[12];
    const float* bn4 = (const float*)d_in[13];
    const float* bn5 = (const float*)d_in[14];
    const float* bn6 = (const float*)d_in[15];
    const float* bn7 = (const float*)d_in[16];
    const float* bn8 = (const float*)d_in[17];
    float* outp = (float*)d_out;

    float *xx, *x1, *x2, *x3, *cat, *h7, *h8, *gmean, *part, *b7;
    int *idx;
    cudaGetSymbolAddress((void**)&xx,  g_xx);
    cudaGetSymbolAddress((void**)&idx, g_idx);
    cudaGetSymbolAddress((void**)&x1,  g_x1);
    cudaGetSymbolAddress((void**)&x2,  g_x2);
    cudaGetSymbolAddress((void**)&x3,  g_x3);
    cudaGetSymbolAddress((void**)&cat, g_cat);
    cudaGetSymbolAddress((void**)&h7,  g_h7);
    cudaGetSymbolAddress((void**)&h8,  g_h8);
    cudaGetSymbolAddress((void**)&gmean, g_gmean);
    cudaGetSymbolAddress((void**)&part,  g_part);
    cudaGetSymbolAddress((void**)&b7,  g_b7);

    int sm1 = ec_smem(3, true), sm2 = ec_smem(64, true), sm3 = ec_smem(64, false);
    cudaFuncSetAttribute(edgeconv_kernel<3,true>,   cudaFuncAttributeMaxDynamicSharedMemorySize, sm1);
    cudaFuncSetAttribute(edgeconv_kernel<64,true>,  cudaFuncAttributeMaxDynamicSharedMemorySize, sm2);
    cudaFuncSetAttribute(edgeconv_kernel<64,false>, cudaFuncAttributeMaxDynamicSharedMemorySize, sm3);

    int smk = (64*67*3 + 64*65 + 64) * 4;   // Qsm + Bh + Bl + Dsm + xxs
    cudaFuncSetAttribute(knn64t_kernel, cudaFuncAttributeMaxDynamicSharedMemorySize, smk);

    // stage 1 (xx of x1 computed inside edgeconv)
    knn3_kernel<<<NPTS/128, 128>>>(x, idx);
    edgeconv_kernel<3,true><<<NPTS/32, 256, sm1>>>(x, idx, W1, bn1, W2, bn2, x1, xx);
    // stage 2
    knn64t_kernel<<<NPTS/64, 128, smk>>>(x1, xx, idx);
    edgeconv_kernel<64,true><<<NPTS/32, 256, sm2>>>(x1, idx, W3, bn3, W4, bn4, x2, xx);
    // stage 3
    knn64t_kernel<<<NPTS/64, 128, smk>>>(x2, xx, idx);
    edgeconv_kernel<64,false><<<NPTS/32, 256, sm3>>>(x2, idx, W5, bn5, nullptr, nullptr, x3, nullptr);
    // global feature (vf never materialized)
    concat192_kernel<<<NPTS*192/256, 256>>>(x1, x2, x3, cat);
    gemm_kernel<<<dim3(1024/128, NPTS/128), 256>>>(cat, 192, W6, 192, bn6, nullptr, nullptr, 1024, 192, 1, part);
    mean2_kernel<<<BB*1024/256, 256>>>(part, gmean, outp);          // g -> out[0:8192]
    // decoder: W7·[g;x1;x2;x3] = (W7[:, :1024]·g) + (W7[:,1024:]·cat)
    bias7_kernel<<<512, 256>>>(gmean, W7, b7);
    gemm_kernel<<<dim3(512/128, NPTS/128), 256>>>(cat, 192, W7 + 1024, 1216, bn7, b7, h7, 512, 192, 1, nullptr);
    gemm_kernel<<<dim3(256/128, NPTS/128), 256>>>(h7, 512, W8, 512, bn8, nullptr, h8, 256, 512, 1, nullptr);
    final_kernel<<<NPTS/8, 256>>>(h8, W9, outp + BB*1024);          // out -> out[8192:]
}

// round 15
// speedup vs baseline: 1.3289x; 1.3289x over previous
#include <cuda_runtime.h>

#define BB 8
#define NN 4096
#define NPTS (BB*NN)
#define KK 20
#define EPS_BN 1e-5f
#define GSZF 1536

// ---- scratch (device globals; no allocation allowed) ----
__device__ float g_xx[NPTS];
__device__ int   g_idx[NPTS*KK];
__device__ float g_x1[NPTS*64];
__device__ float g_x2[NPTS*64];
__device__ float g_x3[NPTS*64];
__device__ float g_cat[(size_t)NPTS*192];
__device__ float g_h7[(size_t)NPTS*512];
__device__ float g_h8[(size_t)NPTS*256];
__device__ float g_gmean[BB*1024];
__device__ float g_part[256*1024];
__device__ float g_b7[BB*512];

// ---- kNN for C=3 with xx fused ----
__global__ __launch_bounds__(128) void knn3_kernel(const float* __restrict__ x,
                                                   int* __restrict__ idxout) {
    constexpr int TILE = 128;
    constexpr int C = 3;
    __shared__ float xs[TILE*C];
    __shared__ float xxs[TILE];
    int tid = threadIdx.x;
    int gpt = blockIdx.x*128 + tid;
    int b = gpt >> 12;
    const float* xb = x + (size_t)b*NN*C;

    float q[C];
    #pragma unroll
    for (int c = 0; c < C; ++c) q[c] = x[(size_t)gpt*C + c];
    float qq = fmaf(q[2], q[2], fmaf(q[1], q[1], fmaf(q[0], q[0], 0.f)));

    float tv[KK]; int ti[KK];
    #pragma unroll
    for (int s = 0; s < KK; ++s) { tv[s] = -3.4e38f; ti[s] = 0; }

    for (int m0 = 0; m0 < NN; m0 += TILE) {
        __syncthreads();
        for (int l = tid; l < TILE*C; l += 128) xs[l] = xb[(size_t)m0*C + l];
        __syncthreads();
        {
            float v0 = xs[tid*3], v1 = xs[tid*3+1], v2 = xs[tid*3+2];
            xxs[tid] = fmaf(v2, v2, fmaf(v1, v1, fmaf(v0, v0, 0.f)));
        }
        __syncthreads();
        #pragma unroll 2
        for (int mm = 0; mm < TILE; ++mm) {
            float dot = 0.f;
            #pragma unroll
            for (int c = 0; c < C; ++c) dot = fmaf(q[c], xs[mm*C + c], dot);
            float v = 2.0f*dot - qq - xxs[mm];
            if (v > tv[KK-1]) {
                float cv = v; int ci = m0 + mm;
                #pragma unroll
                for (int s = 0; s < KK; ++s) {
                    if (cv > tv[s]) {
                        float t1 = tv[s]; int t2 = ti[s];
                        tv[s] = cv; ti[s] = ci; cv = t1; ci = t2;
                    }
                }
            }
        }
    }
    #pragma unroll
    for (int s = 0; s < KK; ++s) idxout[(size_t)gpt*KK + s] = ti[s];
}

// ---- kNN: top-20 of pdist = 2*dot - xx_n - xx_m (C=64, frozen R10 version) ----
template<int C>
__global__ __launch_bounds__(128) void knn_kernel(const float* __restrict__ x,
                                                  const float* __restrict__ xx,
                                                  int* __restrict__ idxout) {
    constexpr int TILE = 128;
    __shared__ float xs[TILE*C];
    __shared__ float xxs[TILE];
    int tid = threadIdx.x;
    int gpt = blockIdx.x*128 + tid;
    int b = gpt >> 12;
    const float* xb  = x  + (size_t)b*NN*C;
    const float* xxb = xx + (size_t)b*NN;

    float q[C];
    #pragma unroll
    for (int c = 0; c < C; ++c) q[c] = x[(size_t)gpt*C + c];
    float qq = xx[gpt];

    float tv[KK]; int ti[KK];
    #pragma unroll
    for (int s = 0; s < KK; ++s) { tv[s] = -3.4e38f; ti[s] = 0; }

    for (int m0 = 0; m0 < NN; m0 += TILE) {
        __syncthreads();
        for (int l = tid; l < TILE*C; l += 128) xs[l] = xb[(size_t)m0*C + l];
        if (tid < TILE) xxs[tid] = xxb[m0 + tid];
        __syncthreads();
        #pragma unroll 2
        for (int mm = 0; mm < TILE; ++mm) {
            float dot;
            if constexpr (C % 8 == 0) {
                float d0 = 0.f, d1 = 0.f;
                const float4* xr = (const float4*)(xs + mm*C);
                #pragma unroll
                for (int c8 = 0; c8 < C/8; ++c8) {
                    float4 v0 = xr[2*c8], v1 = xr[2*c8+1];
                    d0 = fmaf(q[8*c8+0], v0.x, d0);
                    d0 = fmaf(q[8*c8+1], v0.y, d0);
                    d0 = fmaf(q[8*c8+2], v0.z, d0);
                    d0 = fmaf(q[8*c8+3], v0.w, d0);
                    d1 = fmaf(q[8*c8+4], v1.x, d1);
                    d1 = fmaf(q[8*c8+5], v1.y, d1);
                    d1 = fmaf(q[8*c8+6], v1.z, d1);
                    d1 = fmaf(q[8*c8+7], v1.w, d1);
                }
                dot = d0 + d1;
            } else {
                dot = 0.f;
                #pragma unroll
                for (int c = 0; c < C; ++c) dot = fmaf(q[c], xs[mm*C + c], dot);
            }
            float v = 2.0f*dot - qq - xxs[mm];
            if (v > tv[KK-1]) {
                float cv = v; int ci = m0 + mm;
                #pragma unroll
                for (int s = 0; s < KK; ++s) {
                    if (cv > tv[s]) {
                        float t1 = tv[s]; int t2 = ti[s];
                        tv[s] = cv; ti[s] = ci; cv = t1; ci = t2;
                    }
                }
            }
        }
    }
    #pragma unroll
    for (int s = 0; s < KK; ++s) idxout[(size_t)gpt*KK + s] = ti[s];
}

// ---- fused edge-conv, warp-per-point (R13 winner) + dual write into cat ----
template<int CIN, bool TWO>
__global__ __launch_bounds__(256) void edgeconv_kernel(
    const float* __restrict__ x, const int* __restrict__ nbr,
    const float* __restrict__ Wa, const float* __restrict__ bna,
    const float* __restrict__ Wb, const float* __restrict__ bnb,
    float* __restrict__ out, float* __restrict__ xxout,
    float* __restrict__ catout)
{
    constexpr int C2 = 2*CIN;
    extern __shared__ float sm[];
    float* Wat2 = sm;
    float* Wbt2 = Wat2 + C2*64;
    float* bnAs = Wbt2 + (TWO ? 4096 : 0);
    float* bnBs = bnAs + 192;
    float* grp  = bnBs + (TWO ? 192 : 0);

    int tid = threadIdx.x;
    int warp = tid >> 5, o = tid & 31;

    for (int l = tid; l < C2*32; l += 256) {
        int c = l >> 5, o2 = l & 31;
        ((float2*)Wat2)[c*32 + o2] = make_float2(Wa[(size_t)o2*C2 + c], Wa[(size_t)(o2+32)*C2 + c]);
    }
    if (TWO)
        for (int l = tid; l < 64*32; l += 256) {
            int c = l >> 5, o2 = l & 31;
            ((float2*)Wbt2)[c*32 + o2] = make_float2(Wb[(size_t)o2*64 + c], Wb[(size_t)(o2+32)*64 + c]);
        }
    if (tid < 64) {
        float ga = bna[tid], bt = bna[64+tid], mu = bna[128+tid], va = bna[192+tid];
        bnAs[tid] = ga*rsqrtf(va + EPS_BN); bnAs[64+tid] = mu; bnAs[128+tid] = bt;
    } else if (TWO && tid < 128) {
        int t = tid - 64;
        float ga = bnb[t], bt = bnb[64+t], mu = bnb[128+t], va = bnb[192+t];
        bnBs[t] = ga*rsqrtf(va + EPS_BN); bnBs[64+t] = mu; bnBs[128+t] = bt;
    }
    __syncthreads();

    float* gbuf = grp + warp*GSZF;
    float* gcen = gbuf + 20*72;
    int*   gsnb = (int*)(gcen + 68);

    float sA0 = bnAs[o],    mA0 = bnAs[64+o],    bA0 = bnAs[128+o];
    float sA1 = bnAs[o+32], mA1 = bnAs[64+o+32], bA1 = bnAs[128+o+32];
    float sB0=0.f,mB0=0.f,bB0=0.f,sB1=0.f,mB1=0.f,bB1=0.f;
    if (TWO) {
        sB0 = bnBs[o];    mB0 = bnBs[64+o];    bB0 = bnBs[128+o];
        sB1 = bnBs[o+32]; mB1 = bnBs[64+o+32]; bB1 = bnBs[128+o+32];
    }

    int base = (blockIdx.x*8 + warp) * 4;
    for (int p = 0; p < 4; ++p) {
        int gpt = base + p;
        int brow = (gpt >> 12) << 12;
        if (CIN == 64) {
            gcen[o]      = x[(size_t)gpt*CIN + o];
            gcen[o + 32] = x[(size_t)gpt*CIN + o + 32];
        } else {
            if (o < CIN) gcen[o] = x[(size_t)gpt*CIN + o];
        }
        if (o < KK) gsnb[o] = nbr[(size_t)gpt*KK + o];
        __syncwarp();
        if (CIN == 64) {
            float ce0 = gcen[o], ce1 = gcen[o+32];
            #pragma unroll
            for (int j = 0; j < KK; ++j) {
                const float* xr = x + ((size_t)(brow + gsnb[j]))*CIN;
                gbuf[j*72 + o]      = xr[o]      - ce0;
                gbuf[j*72 + o + 32] = xr[o + 32] - ce1;
            }
        } else {
            for (int l = o; l < 3*KK; l += 32) {
                int j = l / 3, c = l - 3*j;
                gbuf[j*72 + c] = x[((size_t)(brow + gsnb[j]))*CIN + c] - gcen[c];
            }
        }
        __syncwarp();
        float cd0 = 0.f, cd1 = 0.f;
        if (CIN == 64) {
            #pragma unroll 4
            for (int c4 = 0; c4 < CIN/4; ++c4) {
                float4 ce = *(const float4*)(gcen + 4*c4);
                float2 w0 = ((const float2*)Wat2)[(CIN + 4*c4 + 0)*32 + o];
                float2 w1 = ((const float2*)Wat2)[(CIN + 4*c4 + 1)*32 + o];
                float2 w2 = ((const float2*)Wat2)[(CIN + 4*c4 + 2)*32 + o];
                float2 w3 = ((const float2*)Wat2)[(CIN + 4*c4 + 3)*32 + o];
                cd0 = fmaf(w0.x, ce.x, cd0); cd1 = fmaf(w0.y, ce.x, cd1);
                cd0 = fmaf(w1.x, ce.y, cd0); cd1 = fmaf(w1.y, ce.y, cd1);
                cd0 = fmaf(w2.x, ce.z, cd0); cd1 = fmaf(w2.y, ce.z, cd1);
                cd0 = fmaf(w3.x, ce.w, cd0); cd1 = fmaf(w3.y, ce.w, cd1);
            }
        } else {
            #pragma unroll
            for (int c = 0; c < CIN; ++c) {
                float2 w = ((const float2*)Wat2)[(CIN + c)*32 + o];
                float ce = gcen[c];
                cd0 = fmaf(w.x, ce, cd0); cd1 = fmaf(w.y, ce, cd1);
            }
        }
        float acc0[KK], acc1[KK];
        #pragma unroll
        for (int j = 0; j < KK; ++j) { acc0[j] = cd0; acc1[j] = cd1; }
        if (CIN == 64) {
            #pragma unroll 1
            for (int c4 = 0; c4 < CIN/4; ++c4) {
                float2 w0 = ((const float2*)Wat2)[(4*c4 + 0)*32 + o];
                float2 w1 = ((const float2*)Wat2)[(4*c4 + 1)*32 + o];
                float2 w2 = ((const float2*)Wat2)[(4*c4 + 2)*32 + o];
                float2 w3 = ((const float2*)Wat2)[(4*c4 + 3)*32 + o];
                #pragma unroll
                for (int j = 0; j < KK; ++j) {
                    float4 d = *(const float4*)(gbuf + j*72 + 4*c4);
                    float a0 = acc0[j], a1 = acc1[j];
                    a0 = fmaf(w0.x, d.x, a0); a1 = fmaf(w0.y, d.x, a1);
                    a0 = fmaf(w1.x, d.y, a0); a1 = fmaf(w1.y, d.y, a1);
                    a0 = fmaf(w2.x, d.z, a0); a1 = fmaf(w2.y, d.z, a1);
                    a0 = fmaf(w3.x, d.w, a0); a1 = fmaf(w3.y, d.w, a1);
                    acc0[j] = a0; acc1[j] = a1;
                }
            }
        } else {
            #pragma unroll
            for (int c = 0; c < CIN; ++c) {
                float2 w = ((const float2*)Wat2)[c*32 + o];
                #pragma unroll
                for (int j = 0; j < KK; ++j) {
                    float d = gbuf[j*72 + c];
                    acc0[j] = fmaf(w.x, d, acc0[j]);
                    acc1[j] = fmaf(w.y, d, acc1[j]);
                }
            }
        }
        float vm0 = -3.4e38f, vm1 = -3.4e38f;
        if (TWO) {
            __syncwarp();
            #pragma unroll
            for (int j = 0; j < KK; ++j) {
                float y0 = (acc0[j] - mA0)*sA0 + bA0; y0 = (y0 >= 0.f) ? y0 : 0.2f*y0;
                float y1 = (acc1[j] - mA1)*sA1 + bA1; y1 = (y1 >= 0.f) ? y1 : 0.2f*y1;
                gbuf[j*72 + o]      = y0;
                gbuf[j*72 + o + 32] = y1;
            }
            __syncwarp();
            float a20[KK], a21[KK];
            #pragma unroll
            for (int j = 0; j < KK; ++j) { a20[j] = 0.f; a21[j] = 0.f; }
            #pragma unroll 1
            for (int c4 = 0; c4 < 16; ++c4) {
                float2 w0 = ((const float2*)Wbt2)[(4*c4 + 0)*32 + o];
                float2 w1 = ((const float2*)Wbt2)[(4*c4 + 1)*32 + o];
                float2 w2 = ((const float2*)Wbt2)[(4*c4 + 2)*32 + o];
                float2 w3 = ((const float2*)Wbt2)[(4*c4 + 3)*32 + o];
                #pragma unroll
                for (int j = 0; j < KK; ++j) {
                    float4 d = *(const float4*)(gbuf + j*72 + 4*c4);
                    float a0 = a20[j], a1 = a21[j];
                    a0 = fmaf(w0.x, d.x, a0); a1 = fmaf(w0.y, d.x, a1);
                    a0 = fmaf(w1.x, d.y, a0); a1 = fmaf(w1.y, d.y, a1);
                    a0 = fmaf(w2.x, d.z, a0); a1 = fmaf(w2.y, d.z, a1);
                    a0 = fmaf(w3.x, d.w, a0); a1 = fmaf(w3.y, d.w, a1);
                    a20[j] = a0; a21[j] = a1;
                }
            }
            #pragma unroll
            for (int j = 0; j < KK; ++j) {
                float y0 = (a20[j] - mB0)*sB0 + bB0; y0 = (y0 >= 0.f) ? y0 : 0.2f*y0;
                float y1 = (a21[j] - mB1)*sB1 + bB1; y1 = (y1 >= 0.f) ? y1 : 0.2f*y1;
                vm0 = fmaxf(vm0, y0); vm1 = fmaxf(vm1, y1);
            }
        } else {
            #pragma unroll
            for (int j = 0; j < KK; ++j) {
                float y0 = (acc0[j] - mA0)*sA0 + bA0; y0 = (y0 >= 0.f) ? y0 : 0.2f*y0;
                float y1 = (acc1[j] - mA1)*sA1 + bA1; y1 = (y1 >= 0.f) ? y1 : 0.2f*y1;
                vm0 = fmaxf(vm0, y0); vm1 = fmaxf(vm1, y1);
            }
        }
        out[(size_t)gpt*64 + o]      = vm0;
        out[(size_t)gpt*64 + o + 32] = vm1;
        if (catout) {
            catout[(size_t)gpt*192 + o]      = vm0;
            catout[(size_t)gpt*192 + o + 32] = vm1;
        }
        if (xxout) {
            float sq = fmaf(vm1, vm1, vm0*vm0);
            #pragma unroll
            for (int off = 16; off; off >>= 1)
                sq += __shfl_down_sync(0xffffffffu, sq, off);
            if (o == 0) xxout[gpt] = sq;
        }
        __syncwarp();
    }
}

// ---- dense GEMM with optional colsum fusion ----
__global__ __launch_bounds__(256) void gemm_kernel(
    const float* __restrict__ A, int lda,
    const float* __restrict__ W, int ldw,
    const float* __restrict__ bn, const float* __restrict__ bias,
    float* __restrict__ out, int Ncols, int Kd, int act,
    float* __restrict__ colsum)
{
    __shared__ float As[8][128];
    __shared__ float Ws[8][128];
    __shared__ float red[16][128];
    int tid = threadIdx.x;
    int bm  = blockIdx.y*128, bn0 = blockIdx.x*128;
    int lr = tid >> 1;
    int lk = (tid & 1)*4;
    int ty = tid >> 4, tx = tid & 15;

    float acc[8][8];
    #pragma unroll
    for (int i = 0; i < 8; ++i)
        #pragma unroll
        for (int j = 0; j < 8; ++j) acc[i][j] = 0.f;

    const float* Ap = A + (size_t)(bm + lr)*lda + lk;
    const float* Wp = W + (size_t)(bn0 + lr)*ldw + lk;

    for (int k0 = 0; k0 < Kd; k0 += 8) {
        float4 av = *(const float4*)(Ap + k0);
        float4 wv = *(const float4*)(Wp + k0);
        __syncthreads();
        As[lk+0][lr] = av.x; As[lk+1][lr] = av.y; As[lk+2][lr] = av.z; As[lk+3][lr] = av.w;
        Ws[lk+0][lr] = wv.x; Ws[lk+1][lr] = wv.y; Ws[lk+2][lr] = wv.z; Ws[lk+3][lr] = wv.w;
        __syncthreads();
        #pragma unroll
        for (int k = 0; k < 8; ++k) {
            float a[8], bb[8];
            *(float4*)(a)    = *(const float4*)&As[k][ty*8];
            *(float4*)(a+4)  = *(const float4*)&As[k][ty*8+4];
            *(float4*)(bb)   = *(const float4*)&Ws[k][tx*8];
            *(float4*)(bb+4) = *(const float4*)&Ws[k][tx*8+4];
            #pragma unroll
            for (int i = 0; i < 8; ++i)
                #pragma unroll
                for (int j = 0; j < 8; ++j) acc[i][j] = fmaf(a[i], bb[j], acc[i][j]);
        }
    }

    float sc[8], mu[8], be[8], bv[8];
    #pragma unroll
    for (int j = 0; j < 8; ++j) {
        int col = bn0 + tx*8 + j;
        if (act) {
            float ga = bn[col], bt = bn[Ncols+col], m = bn[2*Ncols+col], va = bn[3*Ncols+col];
            sc[j] = ga*rsqrtf(va + EPS_BN); mu[j] = m; be[j] = bt;
        }
        bv[j] = bias ? bias[(bm >> 12)*Ncols + col] : 0.f;
    }
    if (colsum) {
        float ps[8];
        #pragma unroll
        for (int j = 0; j < 8; ++j) ps[j] = 0.f;
        #pragma unroll
        for (int i = 0; i < 8; ++i)
            #pragma unroll
            for (int j = 0; j < 8; ++j) {
                float y = acc[i][j] + bv[j];
                if (act) { y = (y - mu[j])*sc[j] + be[j]; y = (y >= 0.f) ? y : 0.2f*y; }
                ps[j] += y;
            }
        #pragma unroll
        for (int j = 0; j < 8; ++j) red[ty][tx*8 + j] = ps[j];
        __syncthreads();
        if (tid < 128) {
            float s = 0.f;
            #pragma unroll
            for (int t = 0; t < 16; ++t) s += red[t][tid];
            colsum[(size_t)blockIdx.y*Ncols + bn0 + tid] = s;
        }
    } else {
        #pragma unroll
        for (int i = 0; i < 8; ++i) {
            int row = bm + ty*8 + i;
            float* orow = out + (size_t)row*Ncols + bn0 + tx*8;
            #pragma unroll
            for (int j = 0; j < 8; ++j) {
                float y = acc[i][j] + bv[j];
                if (act) { y = (y - mu[j])*sc[j] + be[j]; y = (y >= 0.f) ? y : 0.2f*y; }
                orow[j] = y;
            }
        }
    }
}

// ---- mean from per-block column sums ----
__global__ __launch_bounds__(256) void mean2_kernel(const float* __restrict__ part,
                                                    float* __restrict__ gmean,
                                                    float* __restrict__ outg) {
    int i = blockIdx.x*256 + threadIdx.x;
    int b = i >> 10, c = i & 1023;
    float s = 0.f;
    #pragma unroll
    for (int t = 0; t < 32; ++t) s += part[((size_t)(b*32 + t) << 10) + c];
    s *= (1.0f/NN);
    gmean[i] = s;
    outg[i] = s;
}

// ---- b7[b,o] = sum_{c<1024} W7[o,c] * g[b,c] ----
__global__ __launch_bounds__(256) void bias7_kernel(const float* __restrict__ gm,
                                                    const float* __restrict__ W7,
                                                    float* __restrict__ b7) {
    int w = (blockIdx.x*256 + threadIdx.x) >> 5;
    int lane = threadIdx.x & 31;
    int b = w >> 9, o = w & 511;
    const float* gr = gm + (b << 10);
    const float* wr = W7 + (size_t)o*1216;
    float s = 0.f;
    #pragma unroll 4
    for (int c = lane; c < 1024; c += 32) s = fmaf(wr[c], gr[c], s);
    #pragma unroll
    for (int off = 16; off; off >>= 1) s += __shfl_down_sync(0xffffffffu, s, off);
    if (lane == 0) b7[(b << 9) + o] = s;
}

// ---- final 256 -> 3 projection ----
__global__ __launch_bounds__(256) void final_kernel(const float* __restrict__ h,
                                                    const float* __restrict__ W9,
                                                    float* __restrict__ out) {
    int warp = (blockIdx.x*256 + threadIdx.x) >> 5;
    int lane = threadIdx.x & 31;
    const float* hr = h + (size_t)warp*256;
    float p0 = 0.f, p1 = 0.f, p2 = 0.f;
    #pragma unroll
    for (int c0 = 0; c0 < 256; c0 += 32) {
        int c = c0 + lane;
        float hv = hr[c];
        p0 = fmaf(hv, W9[c],       p0);
        p1 = fmaf(hv, W9[256 + c], p1);
        p2 = fmaf(hv, W9[512 + c], p2);
    }
    #pragma unroll
    for (int off = 16; off; off >>= 1) {
        p0 += __shfl_down_sync(0xffffffffu, p0, off);
        p1 += __shfl_down_sync(0xffffffffu, p1, off);
        p2 += __shfl_down_sync(0xffffffffu, p2, off);
    }
    if (lane == 0) {
        out[(size_t)warp*3 + 0] = p0;
        out[(size_t)warp*3 + 1] = p1;
        out[(size_t)warp*3 + 2] = p2;
    }
}

static int ec_smem(int cin, bool two) {
    int c2 = 2*cin;
    return (c2*64 + (two ? 4096 : 0) + 192 + (two ? 192 : 0) + 8*GSZF) * 4;
}

extern "C" void kernel_launch(void* const* d_in, const int* in_sizes, int n_in,
                              void* d_out, int out_size) {
    (void)in_sizes; (void)n_in; (void)out_size;
    const float* x  = (const float*)d_in[0];
    const float* W1 = (const float*)d_in[1];
    const float* W2 = (const float*)d_in[2];
    const float* W3 = (const float*)d_in[3];
    const float* W4 = (const float*)d_in[4];
    const float* W5 = (const float*)d_in[5];
    const float* W6 = (const float*)d_in[6];
    const float* W7 = (const float*)d_in[7];
    const float* W8 = (const float*)d_in[8];
    const float* W9 = (const float*)d_in[9];
    const float* bn1 = (const float*)d_in[10];
    const float* bn2 = (const float*)d_in[11];
    const float* bn3 = (const float*)d_in[12];
    const float* bn4 = (const float*)d_in[13];
    const float* bn5 = (const float*)d_in[14];
    const float* bn6 = (const float*)d_in[15];
    const float* bn7 = (const float*)d_in[16];
    const float* bn8 = (const float*)d_in[17];
    float* outp = (float*)d_out;

    float *xx, *x1, *x2, *x3, *cat, *h7, *h8, *gmean, *part, *b7;
    int *idx;
    cudaGetSymbolAddress((void**)&xx,  g_xx);
    cudaGetSymbolAddress((void**)&idx, g_idx);
    cudaGetSymbolAddress((void**)&x1,  g_x1);
    cudaGetSymbolAddress((void**)&x2,  g_x2);
    cudaGetSymbolAddress((void**)&x3,  g_x3);
    cudaGetSymbolAddress((void**)&cat, g_cat);
    cudaGetSymbolAddress((void**)&h7,  g_h7);
    cudaGetSymbolAddress((void**)&h8,  g_h8);
    cudaGetSymbolAddress((void**)&gmean, g_gmean);
    cudaGetSymbolAddress((void**)&part,  g_part);
    cudaGetSymbolAddress((void**)&b7,  g_b7);

    int sm1 = ec_smem(3, true), sm2 = ec_smem(64, true), sm3 = ec_smem(64, false);
    cudaFuncSetAttribute(edgeconv_kernel<3,true>,   cudaFuncAttributeMaxDynamicSharedMemorySize, sm1);
    cudaFuncSetAttribute(edgeconv_kernel<64,true>,  cudaFuncAttributeMaxDynamicSharedMemorySize, sm2);
    cudaFuncSetAttribute(edgeconv_kernel<64,false>, cudaFuncAttributeMaxDynamicSharedMemorySize, sm3);

    // stage 1 (xx of x1 computed inside edgeconv; cat slice written in-place)
    knn3_kernel<<<NPTS/128, 128>>>(x, idx);
    edgeconv_kernel<3,true><<<NPTS/32, 256, sm1>>>(x, idx, W1, bn1, W2, bn2, x1, xx, cat);
    // stage 2
    knn_kernel<64><<<NPTS/128, 128>>>(x1, xx, idx);
    edgeconv_kernel<64,true><<<NPTS/32, 256, sm2>>>(x1, idx, W3, bn3, W4, bn4, x2, xx, cat + 64);
    // stage 3
    knn_kernel<64><<<NPTS/128, 128>>>(x2, xx, idx);
    edgeconv_kernel<64,false><<<NPTS/32, 256, sm3>>>(x2, idx, W5, bn5, nullptr, nullptr, x3, nullptr, cat + 128);
    // global feature (vf never materialized; cat built by edge-convs)
    gemm_kernel<<<dim3(1024/128, NPTS/128), 256>>>(cat, 192, W6, 192, bn6, nullptr, nullptr, 1024, 192, 1, part);
    mean2_kernel<<<BB*1024/256, 256>>>(part, gmean, outp);          // g -> out[0:8192]
    // decoder: W7·[g;x1;x2;x3] = (W7[:, :1024]·g) + (W7[:,1024:]·cat)
    bias7_kernel<<<512, 256>>>(gmean, W7, b7);
    gemm_kernel<<<dim3(512/128, NPTS/128), 256>>>(cat, 192, W7 + 1024, 1216, bn7, b7, h7, 512, 192, 1, nullptr);
    gemm_kernel<<<dim3(256/128, NPTS/128), 256>>>(h7, 512, W8, 512, bn8, nullptr, h8, 256, 512, 1, nullptr);
    final_kernel<<<NPTS/8, 256>>>(h8, W9, outp + BB*1024);          // out -> out[8192:]
}

// round 16
// speedup vs baseline: 1.4030x; 1.0557x over previous
#include <cuda_runtime.h>

#define BB 8
#define NN 4096
#define NPTS (BB*NN)
#define KK 20
#define EPS_BN 1e-5f
#define GSZF 1536

// ---- scratch (device globals; no allocation allowed) ----
__device__ float g_xx[NPTS];
__device__ int   g_idx[NPTS*KK];
__device__ float g_x1[NPTS*64];
__device__ float g_x2[NPTS*64];
__device__ float g_cat[(size_t)NPTS*192];
__device__ float g_h7[(size_t)NPTS*512];
__device__ float g_h8[(size_t)NPTS*256];
__device__ float g_gmean[BB*1024];
__device__ float g_part[256*1024];
__device__ float g_b7[BB*512];

// ---- kNN for C=3 with xx fused ----
__global__ __launch_bounds__(128) void knn3_kernel(const float* __restrict__ x,
                                                   int* __restrict__ idxout) {
    constexpr int TILE = 128;
    constexpr int C = 3;
    __shared__ float xs[TILE*C];
    __shared__ float xxs[TILE];
    int tid = threadIdx.x;
    int gpt = blockIdx.x*128 + tid;
    int b = gpt >> 12;
    const float* xb = x + (size_t)b*NN*C;

    float q[C];
    #pragma unroll
    for (int c = 0; c < C; ++c) q[c] = x[(size_t)gpt*C + c];
    float qq = fmaf(q[2], q[2], fmaf(q[1], q[1], fmaf(q[0], q[0], 0.f)));

    float tv[KK]; int ti[KK];
    #pragma unroll
    for (int s = 0; s < KK; ++s) { tv[s] = -3.4e38f; ti[s] = 0; }

    for (int m0 = 0; m0 < NN; m0 += TILE) {
        __syncthreads();
        for (int l = tid; l < TILE*C; l += 128) xs[l] = xb[(size_t)m0*C + l];
        __syncthreads();
        {
            float v0 = xs[tid*3], v1 = xs[tid*3+1], v2 = xs[tid*3+2];
            xxs[tid] = fmaf(v2, v2, fmaf(v1, v1, fmaf(v0, v0, 0.f)));
        }
        __syncthreads();
        #pragma unroll 2
        for (int mm = 0; mm < TILE; ++mm) {
            float dot = 0.f;
            #pragma unroll
            for (int c = 0; c < C; ++c) dot = fmaf(q[c], xs[mm*C + c], dot);
            float v = 2.0f*dot - qq - xxs[mm];
            if (v > tv[KK-1]) {
                float cv = v; int ci = m0 + mm;
                #pragma unroll
                for (int s = 0; s < KK; ++s) {
                    if (cv > tv[s]) {
                        float t1 = tv[s]; int t2 = ti[s];
                        tv[s] = cv; ti[s] = ci; cv = t1; ci = t2;
                    }
                }
            }
        }
    }
    #pragma unroll
    for (int s = 0; s < KK; ++s) idxout[(size_t)gpt*KK + s] = ti[s];
}

// ---- kNN: top-20 of pdist = 2*dot - xx_n - xx_m (C=64, frozen) ----
template<int C>
__global__ __launch_bounds__(128) void knn_kernel(const float* __restrict__ x,
                                                  const float* __restrict__ xx,
                                                  int* __restrict__ idxout) {
    constexpr int TILE = 128;
    __shared__ float xs[TILE*C];
    __shared__ float xxs[TILE];
    int tid = threadIdx.x;
    int gpt = blockIdx.x*128 + tid;
    int b = gpt >> 12;
    const float* xb  = x  + (size_t)b*NN*C;
    const float* xxb = xx + (size_t)b*NN;

    float q[C];
    #pragma unroll
    for (int c = 0; c < C; ++c) q[c] = x[(size_t)gpt*C + c];
    float qq = xx[gpt];

    float tv[KK]; int ti[KK];
    #pragma unroll
    for (int s = 0; s < KK; ++s) { tv[s] = -3.4e38f; ti[s] = 0; }

    for (int m0 = 0; m0 < NN; m0 += TILE) {
        __syncthreads();
        for (int l = tid; l < TILE*C; l += 128) xs[l] = xb[(size_t)m0*C + l];
        if (tid < TILE) xxs[tid] = xxb[m0 + tid];
        __syncthreads();
        #pragma unroll 2
        for (int mm = 0; mm < TILE; ++mm) {
            float dot;
            if constexpr (C % 8 == 0) {
                float d0 = 0.f, d1 = 0.f;
                const float4* xr = (const float4*)(xs + mm*C);
                #pragma unroll
                for (int c8 = 0; c8 < C/8; ++c8) {
                    float4 v0 = xr[2*c8], v1 = xr[2*c8+1];
                    d0 = fmaf(q[8*c8+0], v0.x, d0);
                    d0 = fmaf(q[8*c8+1], v0.y, d0);
                    d0 = fmaf(q[8*c8+2], v0.z, d0);
                    d0 = fmaf(q[8*c8+3], v0.w, d0);
                    d1 = fmaf(q[8*c8+4], v1.x, d1);
                    d1 = fmaf(q[8*c8+5], v1.y, d1);
                    d1 = fmaf(q[8*c8+6], v1.z, d1);
                    d1 = fmaf(q[8*c8+7], v1.w, d1);
                }
                dot = d0 + d1;
            } else {
                dot = 0.f;
                #pragma unroll
                for (int c = 0; c < C; ++c) dot = fmaf(q[c], xs[mm*C + c], dot);
            }
            float v = 2.0f*dot - qq - xxs[mm];
            if (v > tv[KK-1]) {
                float cv = v; int ci = m0 + mm;
                #pragma unroll
                for (int s = 0; s < KK; ++s) {
                    if (cv > tv[s]) {
                        float t1 = tv[s]; int t2 = ti[s];
                        tv[s] = cv; ti[s] = ci; cv = t1; ci = t2;
                    }
                }
            }
        }
    }
    #pragma unroll
    for (int s = 0; s < KK; ++s) idxout[(size_t)gpt*KK + s] = ti[s];
}

// ---- fused edge-conv, warp-per-point (R13 winner; ldo parameterized) ----
template<int CIN, bool TWO>
__global__ __launch_bounds__(256) void edgeconv_kernel(
    const float* __restrict__ x, const int* __restrict__ nbr,
    const float* __restrict__ Wa, const float* __restrict__ bna,
    const float* __restrict__ Wb, const float* __restrict__ bnb,
    float* __restrict__ out, int ldo, float* __restrict__ xxout)
{
    constexpr int C2 = 2*CIN;
    extern __shared__ float sm[];
    float* Wat2 = sm;
    float* Wbt2 = Wat2 + C2*64;
    float* bnAs = Wbt2 + (TWO ? 4096 : 0);
    float* bnBs = bnAs + 192;
    float* grp  = bnBs + (TWO ? 192 : 0);

    int tid = threadIdx.x;
    int warp = tid >> 5, o = tid & 31;

    for (int l = tid; l < C2*32; l += 256) {
        int c = l >> 5, o2 = l & 31;
        ((float2*)Wat2)[c*32 + o2] = make_float2(Wa[(size_t)o2*C2 + c], Wa[(size_t)(o2+32)*C2 + c]);
    }
    if (TWO)
        for (int l = tid; l < 64*32; l += 256) {
            int c = l >> 5, o2 = l & 31;
            ((float2*)Wbt2)[c*32 + o2] = make_float2(Wb[(size_t)o2*64 + c], Wb[(size_t)(o2+32)*64 + c]);
        }
    if (tid < 64) {
        float ga = bna[tid], bt = bna[64+tid], mu = bna[128+tid], va = bna[192+tid];
        bnAs[tid] = ga*rsqrtf(va + EPS_BN); bnAs[64+tid] = mu; bnAs[128+tid] = bt;
    } else if (TWO && tid < 128) {
        int t = tid - 64;
        float ga = bnb[t], bt = bnb[64+t], mu = bnb[128+t], va = bnb[192+t];
        bnBs[t] = ga*rsqrtf(va + EPS_BN); bnBs[64+t] = mu; bnBs[128+t] = bt;
    }
    __syncthreads();

    float* gbuf = grp + warp*GSZF;
    float* gcen = gbuf + 20*72;
    int*   gsnb = (int*)(gcen + 68);

    float sA0 = bnAs[o],    mA0 = bnAs[64+o],    bA0 = bnAs[128+o];
    float sA1 = bnAs[o+32], mA1 = bnAs[64+o+32], bA1 = bnAs[128+o+32];
    float sB0=0.f,mB0=0.f,bB0=0.f,sB1=0.f,mB1=0.f,bB1=0.f;
    if (TWO) {
        sB0 = bnBs[o];    mB0 = bnBs[64+o];    bB0 = bnBs[128+o];
        sB1 = bnBs[o+32]; mB1 = bnBs[64+o+32]; bB1 = bnBs[128+o+32];
    }

    int base = (blockIdx.x*8 + warp) * 4;
    for (int p = 0; p < 4; ++p) {
        int gpt = base + p;
        int brow = (gpt >> 12) << 12;
        if (CIN == 64) {
            gcen[o]      = x[(size_t)gpt*CIN + o];
            gcen[o + 32] = x[(size_t)gpt*CIN + o + 32];
        } else {
            if (o < CIN) gcen[o] = x[(size_t)gpt*CIN + o];
        }
        if (o < KK) gsnb[o] = nbr[(size_t)gpt*KK + o];
        __syncwarp();
        if (CIN == 64) {
            float ce0 = gcen[o], ce1 = gcen[o+32];
            #pragma unroll
            for (int j = 0; j < KK; ++j) {
                const float* xr = x + ((size_t)(brow + gsnb[j]))*CIN;
                gbuf[j*72 + o]      = xr[o]      - ce0;
                gbuf[j*72 + o + 32] = xr[o + 32] - ce1;
            }
        } else {
            for (int l = o; l < 3*KK; l += 32) {
                int j = l / 3, c = l - 3*j;
                gbuf[j*72 + c] = x[((size_t)(brow + gsnb[j]))*CIN + c] - gcen[c];
            }
        }
        __syncwarp();
        float cd0 = 0.f, cd1 = 0.f;
        if (CIN == 64) {
            #pragma unroll 4
            for (int c4 = 0; c4 < CIN/4; ++c4) {
                float4 ce = *(const float4*)(gcen + 4*c4);
                float2 w0 = ((const float2*)Wat2)[(CIN + 4*c4 + 0)*32 + o];
                float2 w1 = ((const float2*)Wat2)[(CIN + 4*c4 + 1)*32 + o];
                float2 w2 = ((const float2*)Wat2)[(CIN + 4*c4 + 2)*32 + o];
                float2 w3 = ((const float2*)Wat2)[(CIN + 4*c4 + 3)*32 + o];
                cd0 = fmaf(w0.x, ce.x, cd0); cd1 = fmaf(w0.y, ce.x, cd1);
                cd0 = fmaf(w1.x, ce.y, cd0); cd1 = fmaf(w1.y, ce.y, cd1);
                cd0 = fmaf(w2.x, ce.z, cd0); cd1 = fmaf(w2.y, ce.z, cd1);
                cd0 = fmaf(w3.x, ce.w, cd0); cd1 = fmaf(w3.y, ce.w, cd1);
            }
        } else {
            #pragma unroll
            for (int c = 0; c < CIN; ++c) {
                float2 w = ((const float2*)Wat2)[(CIN + c)*32 + o];
                float ce = gcen[c];
                cd0 = fmaf(w.x, ce, cd0); cd1 = fmaf(w.y, ce, cd1);
            }
        }
        float acc0[KK], acc1[KK];
        #pragma unroll
        for (int j = 0; j < KK; ++j) { acc0[j] = cd0; acc1[j] = cd1; }
        if (CIN == 64) {
            #pragma unroll 1
            for (int c4 = 0; c4 < CIN/4; ++c4) {
                float2 w0 = ((const float2*)Wat2)[(4*c4 + 0)*32 + o];
                float2 w1 = ((const float2*)Wat2)[(4*c4 + 1)*32 + o];
                float2 w2 = ((const float2*)Wat2)[(4*c4 + 2)*32 + o];
                float2 w3 = ((const float2*)Wat2)[(4*c4 + 3)*32 + o];
                #pragma unroll
                for (int j = 0; j < KK; ++j) {
                    float4 d = *(const float4*)(gbuf + j*72 + 4*c4);
                    float a0 = acc0[j], a1 = acc1[j];
                    a0 = fmaf(w0.x, d.x, a0); a1 = fmaf(w0.y, d.x, a1);
                    a0 = fmaf(w1.x, d.y, a0); a1 = fmaf(w1.y, d.y, a1);
                    a0 = fmaf(w2.x, d.z, a0); a1 = fmaf(w2.y, d.z, a1);
                    a0 = fmaf(w3.x, d.w, a0); a1 = fmaf(w3.y, d.w, a1);
                    acc0[j] = a0; acc1[j] = a1;
                }
            }
        } else {
            #pragma unroll
            for (int c = 0; c < CIN; ++c) {
                float2 w = ((const float2*)Wat2)[c*32 + o];
                #pragma unroll
                for (int j = 0; j < KK; ++j) {
                    float d = gbuf[j*72 + c];
                    acc0[j] = fmaf(w.x, d, acc0[j]);
                    acc1[j] = fmaf(w.y, d, acc1[j]);
                }
            }
        }
        float vm0 = -3.4e38f, vm1 = -3.4e38f;
        if (TWO) {
            __syncwarp();
            #pragma unroll
            for (int j = 0; j < KK; ++j) {
                float y0 = (acc0[j] - mA0)*sA0 + bA0; y0 = (y0 >= 0.f) ? y0 : 0.2f*y0;
                float y1 = (acc1[j] - mA1)*sA1 + bA1; y1 = (y1 >= 0.f) ? y1 : 0.2f*y1;
                gbuf[j*72 + o]      = y0;
                gbuf[j*72 + o + 32] = y1;
            }
            __syncwarp();
            float a20[KK], a21[KK];
            #pragma unroll
            for (int j = 0; j < KK; ++j) { a20[j] = 0.f; a21[j] = 0.f; }
            #pragma unroll 1
            for (int c4 = 0; c4 < 16; ++c4) {
                float2 w0 = ((const float2*)Wbt2)[(4*c4 + 0)*32 + o];
                float2 w1 = ((const float2*)Wbt2)[(4*c4 + 1)*32 + o];
                float2 w2 = ((const float2*)Wbt2)[(4*c4 + 2)*32 + o];
                float2 w3 = ((const float2*)Wbt2)[(4*c4 + 3)*32 + o];
                #pragma unroll
                for (int j = 0; j < KK; ++j) {
                    float4 d = *(const float4*)(gbuf + j*72 + 4*c4);
                    float a0 = a20[j], a1 = a21[j];
                    a0 = fmaf(w0.x, d.x, a0); a1 = fmaf(w0.y, d.x, a1);
                    a0 = fmaf(w1.x, d.y, a0); a1 = fmaf(w1.y, d.y, a1);
                    a0 = fmaf(w2.x, d.z, a0); a1 = fmaf(w2.y, d.z, a1);
                    a0 = fmaf(w3.x, d.w, a0); a1 = fmaf(w3.y, d.w, a1);
                    a20[j] = a0; a21[j] = a1;
                }
            }
            #pragma unroll
            for (int j = 0; j < KK; ++j) {
                float y0 = (a20[j] - mB0)*sB0 + bB0; y0 = (y0 >= 0.f) ? y0 : 0.2f*y0;
                float y1 = (a21[j] - mB1)*sB1 + bB1; y1 = (y1 >= 0.f) ? y1 : 0.2f*y1;
                vm0 = fmaxf(vm0, y0); vm1 = fmaxf(vm1, y1);
            }
        } else {
            #pragma unroll
            for (int j = 0; j < KK; ++j) {
                float y0 = (acc0[j] - mA0)*sA0 + bA0; y0 = (y0 >= 0.f) ? y0 : 0.2f*y0;
                float y1 = (acc1[j] - mA1)*sA1 + bA1; y1 = (y1 >= 0.f) ? y1 : 0.2f*y1;
                vm0 = fmaxf(vm0, y0); vm1 = fmaxf(vm1, y1);
            }
        }
        out[(size_t)gpt*ldo + o]      = vm0;
        out[(size_t)gpt*ldo + o + 32] = vm1;
        if (xxout) {
            float sq = fmaf(vm1, vm1, vm0*vm0);
            #pragma unroll
            for (int off = 16; off; off >>= 1)
                sq += __shfl_down_sync(0xffffffffu, sq, off);
            if (o == 0) xxout[gpt] = sq;
        }
        __syncwarp();
    }
}

// ---- dense GEMM with optional colsum fusion ----
__global__ __launch_bounds__(256) void gemm_kernel(
    const float* __restrict__ A, int lda,
    const float* __restrict__ W, int ldw,
    const float* __restrict__ bn, const float* __restrict__ bias,
    float* __restrict__ out, int Ncols, int Kd, int act,
    float* __restrict__ colsum)
{
    __shared__ float As[8][128];
    __shared__ float Ws[8][128];
    __shared__ float red[16][128];
    int tid = threadIdx.x;
    int bm  = blockIdx.y*128, bn0 = blockIdx.x*128;
    int lr = tid >> 1;
    int lk = (tid & 1)*4;
    int ty = tid >> 4, tx = tid & 15;

    float acc[8][8];
    #pragma unroll
    for (int i = 0; i < 8; ++i)
        #pragma unroll
        for (int j = 0; j < 8; ++j) acc[i][j] = 0.f;

    const float* Ap = A + (size_t)(bm + lr)*lda + lk;
    const float* Wp = W + (size_t)(bn0 + lr)*ldw + lk;

    for (int k0 = 0; k0 < Kd; k0 += 8) {
        float4 av = *(const float4*)(Ap + k0);
        float4 wv = *(const float4*)(Wp + k0);
        __syncthreads();
        As[lk+0][lr] = av.x; As[lk+1][lr] = av.y; As[lk+2][lr] = av.z; As[lk+3][lr] = av.w;
        Ws[lk+0][lr] = wv.x; Ws[lk+1][lr] = wv.y; Ws[lk+2][lr] = wv.z; Ws[lk+3][lr] = wv.w;
        __syncthreads();
        #pragma unroll
        for (int k = 0; k < 8; ++k) {
            float a[8], bb[8];
            *(float4*)(a)    = *(const float4*)&As[k][ty*8];
            *(float4*)(a+4)  = *(const float4*)&As[k][ty*8+4];
            *(float4*)(bb)   = *(const float4*)&Ws[k][tx*8];
            *(float4*)(bb+4) = *(const float4*)&Ws[k][tx*8+4];
            #pragma unroll
            for (int i = 0; i < 8; ++i)
                #pragma unroll
                for (int j = 0; j < 8; ++j) acc[i][j] = fmaf(a[i], bb[j], acc[i][j]);
        }
    }

    float sc[8], mu[8], be[8], bv[8];
    #pragma unroll
    for (int j = 0; j < 8; ++j) {
        int col = bn0 + tx*8 + j;
        if (act) {
            float ga = bn[col], bt = bn[Ncols+col], m = bn[2*Ncols+col], va = bn[3*Ncols+col];
            sc[j] = ga*rsqrtf(va + EPS_BN); mu[j] = m; be[j] = bt;
        }
        bv[j] = bias ? bias[(bm >> 12)*Ncols + col] : 0.f;
    }
    if (colsum) {
        float ps[8];
        #pragma unroll
        for (int j = 0; j < 8; ++j) ps[j] = 0.f;
        #pragma unroll
        for (int i = 0; i < 8; ++i)
            #pragma unroll
            for (int j = 0; j < 8; ++j) {
                float y = acc[i][j] + bv[j];
                if (act) { y = (y - mu[j])*sc[j] + be[j]; y = (y >= 0.f) ? y : 0.2f*y; }
                ps[j] += y;
            }
        #pragma unroll
        for (int j = 0; j < 8; ++j) red[ty][tx*8 + j] = ps[j];
        __syncthreads();
        if (tid < 128) {
            float s = 0.f;
            #pragma unroll
            for (int t = 0; t < 16; ++t) s += red[t][tid];
            colsum[(size_t)blockIdx.y*Ncols + bn0 + tid] = s;
        }
    } else {
        #pragma unroll
        for (int i = 0; i < 8; ++i) {
            int row = bm + ty*8 + i;
            float* orow = out + (size_t)row*Ncols + bn0 + tx*8;
            #pragma unroll
            for (int j = 0; j < 8; ++j) {
                float y = acc[i][j] + bv[j];
                if (act) { y = (y - mu[j])*sc[j] + be[j]; y = (y >= 0.f) ? y : 0.2f*y; }
                orow[j] = y;
            }
        }
    }
}

// ---- concat [x1|x2] -> cat cols 0..127 (x3 written in place by edgeconv) ----
__global__ __launch_bounds__(256) void concat128_kernel(
    const float* __restrict__ x1, const float* __restrict__ x2,
    float* __restrict__ cat)
{
    int i4 = blockIdx.x*256 + threadIdx.x;    // NPTS*32 float4s
    int pt = i4 >> 5, c4 = i4 & 31;
    float4 v = (c4 < 16) ? ((const float4*)(x1 + (size_t)pt*64))[c4]
                         : ((const float4*)(x2 + (size_t)pt*64))[c4 - 16];
    *(float4*)(cat + (size_t)pt*192 + 4*c4) = v;
}

// ---- mean from per-block column sums ----
__global__ __launch_bounds__(256) void mean2_kernel(const float* __restrict__ part,
                                                    float* __restrict__ gmean,
                                                    float* __restrict__ outg) {
    int i = blockIdx.x*256 + threadIdx.x;
    int b = i >> 10, c = i & 1023;
    float s = 0.f;
    #pragma unroll
    for (int t = 0; t < 32; ++t) s += part[((size_t)(b*32 + t) << 10) + c];
    s *= (1.0f/NN);
    gmean[i] = s;
    outg[i] = s;
}

// ---- b7[b,o] = sum_{c<1024} W7[o,c] * g[b,c] ----
__global__ __launch_bounds__(256) void bias7_kernel(const float* __restrict__ gm,
                                                    const float* __restrict__ W7,
                                                    float* __restrict__ b7) {
    int w = (blockIdx.x*256 + threadIdx.x) >> 5;
    int lane = threadIdx.x & 31;
    int b = w >> 9, o = w & 511;
    const float* gr = gm + (b << 10);
    const float* wr = W7 + (size_t)o*1216;
    float s = 0.f;
    #pragma unroll 4
    for (int c = lane; c < 1024; c += 32) s = fmaf(wr[c], gr[c], s);
    #pragma unroll
    for (int off = 16; off; off >>= 1) s += __shfl_down_sync(0xffffffffu, s, off);
    if (lane == 0) b7[(b << 9) + o] = s;
}

// ---- final 256 -> 3 projection ----
__global__ __launch_bounds__(256) void final_kernel(const float* __restrict__ h,
                                                    const float* __restrict__ W9,
                                                    float* __restrict__ out) {
    int warp = (blockIdx.x*256 + threadIdx.x) >> 5;
    int lane = threadIdx.x & 31;
    const float* hr = h + (size_t)warp*256;
    float p0 = 0.f, p1 = 0.f, p2 = 0.f;
    #pragma unroll
    for (int c0 = 0; c0 < 256; c0 += 32) {
        int c = c0 + lane;
        float hv = hr[c];
        p0 = fmaf(hv, W9[c],       p0);
        p1 = fmaf(hv, W9[256 + c], p1);
        p2 = fmaf(hv, W9[512 + c], p2);
    }
    #pragma unroll
    for (int off = 16; off; off >>= 1) {
        p0 += __shfl_down_sync(0xffffffffu, p0, off);
        p1 += __shfl_down_sync(0xffffffffu, p1, off);
        p2 += __shfl_down_sync(0xffffffffu, p2, off);
    }
    if (lane == 0) {
        out[(size_t)warp*3 + 0] = p0;
        out[(size_t)warp*3 + 1] = p1;
        out[(size_t)warp*3 + 2] = p2;
    }
}

static int ec_smem(int cin, bool two) {
    int c2 = 2*cin;
    return (c2*64 + (two ? 4096 : 0) + 192 + (two ? 192 : 0) + 8*GSZF) * 4;
}

extern "C" void kernel_launch(void* const* d_in, const int* in_sizes, int n_in,
                              void* d_out, int out_size) {
    (void)in_sizes; (void)n_in; (void)out_size;
    const float* x  = (const float*)d_in[0];
    const float* W1 = (const float*)d_in[1];
    const float* W2 = (const float*)d_in[2];
    const float* W3 = (const float*)d_in[3];
    const float* W4 = (const float*)d_in[4];
    const float* W5 = (const float*)d_in[5];
    const float* W6 = (const float*)d_in[6];
    const float* W7 = (const float*)d_in[7];
    const float* W8 = (const float*)d_in[8];
    const float* W9 = (const float*)d_in[9];
    const float* bn1 = (const float*)d_in[10];
    const float* bn2 = (const float*)d_in[11];
    const float* bn3 = (const float*)d_in[12];
    const float* bn4 = (const float*)d_in[13];
    const float* bn5 = (const float*)d_in[14];
    const float* bn6 = (const float*)d_in[15];
    const float* bn7 = (const float*)d_in[16];
    const float* bn8 = (const float*)d_in[17];
    float* outp = (float*)d_out;

    float *xx, *x1, *x2, *cat, *h7, *h8, *gmean, *part, *b7;
    int *idx;
    cudaGetSymbolAddress((void**)&xx,  g_xx);
    cudaGetSymbolAddress((void**)&idx, g_idx);
    cudaGetSymbolAddress((void**)&x1,  g_x1);
    cudaGetSymbolAddress((void**)&x2,  g_x2);
    cudaGetSymbolAddress((void**)&cat, g_cat);
    cudaGetSymbolAddress((void**)&h7,  g_h7);
    cudaGetSymbolAddress((void**)&h8,  g_h8);
    cudaGetSymbolAddress((void**)&gmean, g_gmean);
    cudaGetSymbolAddress((void**)&part,  g_part);
    cudaGetSymbolAddress((void**)&b7,  g_b7);

    int sm1 = ec_smem(3, true), sm2 = ec_smem(64, true), sm3 = ec_smem(64, false);
    cudaFuncSetAttribute(edgeconv_kernel<3,true>,   cudaFuncAttributeMaxDynamicSharedMemorySize, sm1);
    cudaFuncSetAttribute(edgeconv_kernel<64,true>,  cudaFuncAttributeMaxDynamicSharedMemorySize, sm2);
    cudaFuncSetAttribute(edgeconv_kernel<64,false>, cudaFuncAttributeMaxDynamicSharedMemorySize, sm3);

    // stage 1 (xx of x1 computed inside edgeconv)
    knn3_kernel<<<NPTS/128, 128>>>(x, idx);
    edgeconv_kernel<3,true><<<NPTS/32, 256, sm1>>>(x, idx, W1, bn1, W2, bn2, x1, 64, xx);
    // stage 2
    knn_kernel<64><<<NPTS/128, 128>>>(x1, xx, idx);
    edgeconv_kernel<64,true><<<NPTS/32, 256, sm2>>>(x1, idx, W3, bn3, W4, bn4, x2, 64, xx);
    // stage 3: output written straight into cat cols 128..191 (x3 only feeds cat)
    knn_kernel<64><<<NPTS/128, 128>>>(x2, xx, idx);
    edgeconv_kernel<64,false><<<NPTS/32, 256, sm3>>>(x2, idx, W5, bn5, nullptr, nullptr, cat + 128, 192, nullptr);
    // cat cols 0..127 from x1|x2 (vectorized)
    concat128_kernel<<<NPTS*32/256, 256>>>(x1, x2, cat);
    gemm_kernel<<<dim3(1024/128, NPTS/128), 256>>>(cat, 192, W6, 192, bn6, nullptr, nullptr, 1024, 192, 1, part);
    mean2_kernel<<<BB*1024/256, 256>>>(part, gmean, outp);          // g -> out[0:8192]
    // decoder: W7·[g;x1;x2;x3] = (W7[:, :1024]·g) + (W7[:,1024:]·cat)
    bias7_kernel<<<512, 256>>>(gmean, W7, b7);
    gemm_kernel<<<dim3(512/128, NPTS/128), 256>>>(cat, 192, W7 + 1024, 1216, bn7, b7, h7, 512, 192, 1, nullptr);
    gemm_kernel<<<dim3(256/128, NPTS/128), 256>>>(h7, 512, W8, 512, bn8, nullptr, h8, 256, 512, 1, nullptr);
    final_kernel<<<NPTS/8, 256>>>(h8, W9, outp + BB*1024);          // out -> out[8192:]
}